// round 6
// baseline (speedup 1.0000x reference)
#include <cuda_runtime.h>
#include <math.h>

#define LN_EPS 1e-5f

// Problem constants
constexpr int CB = 4, CS = 2048, CD = 2048, CF = 8192;
constexpr int CM = CB * CS;      // 8192 tokens
constexpr int MCHUNK = 1024;     // M rows per pipeline chunk
constexpr int NCHUNKS = CM / MCHUNK;

// GEMM tiling
constexpr int BM = 128, BN = 64, BK = 16;
constexpr int TM = 8, TN = 4;
constexpr int THREADS = (BM / TM) * (BN / TN);  // 256

// Scratch (device globals): 2x32MB + 2x8MB = 80 MB total.
__device__ __align__(16) float g_up_re[(size_t)MCHUNK * CF];
__device__ __align__(16) float g_up_im[(size_t)MCHUNK * CF];
__device__ __align__(16) float g_dn_re[(size_t)MCHUNK * CD];
__device__ __align__(16) float g_dn_im[(size_t)MCHUNK * CD];

__device__ __forceinline__ float4 ld4_guard(const float* p, size_t off, size_t lim) {
    if (off + 4 <= lim) return *reinterpret_cast<const float4*>(p + off);
    float4 z; z.x = z.y = z.z = z.w = 0.f;
    return z;
}

// Complex NT GEMM: C[m,n] = sum_k A[m,k] * B[n,k]
// PHASE 0: A = inputs (rows m_base+..), C = g_up (chunk-local), bias+modrelu epi.
// PHASE 1: A = g_up (chunk-local), C = g_dn (chunk-local), plain store.
template <int PHASE>
__global__ void __launch_bounds__(THREADS)
cgemm_nt(const float* __restrict__ Are, const float* __restrict__ Aim,
         const float* __restrict__ Bre, const float* __restrict__ Bim,
         const float* __restrict__ bias_re, const float* __restrict__ bias_im,
         const float* __restrict__ mrb,
         int m_base, int N, int K,
         size_t a_lim, size_t b_lim, size_t bias_lim) {
    __shared__ __align__(16) float As_re[BK][BM + 4];
    __shared__ __align__(16) float As_im[BK][BM + 4];
    __shared__ __align__(16) float Bs_re[BK][BN + 4];
    __shared__ __align__(16) float Bs_im[BK][BN + 4];

    const int tid = threadIdx.x;
    const int tx = tid % (BN / TN);
    const int ty = tid / (BN / TN);
    const int m0 = blockIdx.y * BM;   // chunk-local row base
    const int n0 = blockIdx.x * BN;

    const float* Ar = (PHASE == 0) ? Are : g_up_re;
    const float* Ai = (PHASE == 0) ? Aim : g_up_im;
    const size_t a_row0 = (PHASE == 0) ? (size_t)m_base : 0;

    const bool a_ok = (a_row0 + m0 + BM) * (size_t)K <= a_lim;
    const bool b_ok = ((size_t)n0 + BN) * (size_t)K <= b_lim;

    float cre[TM][TN], cim[TM][TN];
#pragma unroll
    for (int i = 0; i < TM; i++)
#pragma unroll
        for (int j = 0; j < TN; j++) { cre[i][j] = 0.f; cim[i][j] = 0.f; }

    for (int k0 = 0; k0 < K; k0 += BK) {
#pragma unroll
        for (int p = 0; p < 2; p++) {
            int idx = tid + p * THREADS;
            int row = idx >> 2;
            int kk = (idx & 3) * 4;
            const size_t off = (a_row0 + m0 + row) * (size_t)K + k0 + kk;
            float4 ar, ai;
            if (a_ok) {
                ar = *reinterpret_cast<const float4*>(Ar + off);
                ai = *reinterpret_cast<const float4*>(Ai + off);
            } else {
                ar = ld4_guard(Ar, off, a_lim);
                ai = ld4_guard(Ai, off, a_lim);
            }
            As_re[kk + 0][row] = ar.x; As_re[kk + 1][row] = ar.y;
            As_re[kk + 2][row] = ar.z; As_re[kk + 3][row] = ar.w;
            As_im[kk + 0][row] = ai.x; As_im[kk + 1][row] = ai.y;
            As_im[kk + 2][row] = ai.z; As_im[kk + 3][row] = ai.w;
        }
        {
            int row = tid >> 2;
            int kk = (tid & 3) * 4;
            const size_t off = (size_t)(n0 + row) * K + k0 + kk;
            float4 br, bi;
            if (b_ok) {
                br = *reinterpret_cast<const float4*>(Bre + off);
                bi = *reinterpret_cast<const float4*>(Bim + off);
            } else {
                br = ld4_guard(Bre, off, b_lim);
                bi = ld4_guard(Bim, off, b_lim);
            }
            Bs_re[kk + 0][row] = br.x; Bs_re[kk + 1][row] = br.y;
            Bs_re[kk + 2][row] = br.z; Bs_re[kk + 3][row] = br.w;
            Bs_im[kk + 0][row] = bi.x; Bs_im[kk + 1][row] = bi.y;
            Bs_im[kk + 2][row] = bi.z; Bs_im[kk + 3][row] = bi.w;
        }
        __syncthreads();

#pragma unroll
        for (int k = 0; k < BK; k++) {
            float ar[TM], ai[TM], br[TN], bi[TN];
#pragma unroll
            for (int i = 0; i < TM; i += 4) {
                *reinterpret_cast<float4*>(&ar[i]) =
                    *reinterpret_cast<const float4*>(&As_re[k][ty * TM + i]);
                *reinterpret_cast<float4*>(&ai[i]) =
                    *reinterpret_cast<const float4*>(&As_im[k][ty * TM + i]);
            }
            *reinterpret_cast<float4*>(&br[0]) =
                *reinterpret_cast<const float4*>(&Bs_re[k][tx * TN]);
            *reinterpret_cast<float4*>(&bi[0]) =
                *reinterpret_cast<const float4*>(&Bs_im[k][tx * TN]);
#pragma unroll
            for (int i = 0; i < TM; i++) {
#pragma unroll
                for (int j = 0; j < TN; j++) {
                    cre[i][j] = fmaf(ar[i], br[j], cre[i][j]);
                    cre[i][j] = fmaf(-ai[i], bi[j], cre[i][j]);
                    cim[i][j] = fmaf(ar[i], bi[j], cim[i][j]);
                    cim[i][j] = fmaf(ai[i], br[j], cim[i][j]);
                }
            }
        }
        __syncthreads();
    }

    const int n = n0 + tx * TN;
    const bool bias_ok = (PHASE != 0) || ((size_t)n0 + BN <= bias_lim);
#pragma unroll
    for (int i = 0; i < TM; i++) {
        const int mloc = m0 + ty * TM + i;
        float r[TN], q[TN];
        if (PHASE == 0) {
#pragma unroll
            for (int j = 0; j < TN; j++) {
                float bre = 0.f, bim = 0.f, mb = 0.f;
                if (bias_ok) {
                    bre = bias_re[n + j]; bim = bias_im[n + j]; mb = mrb[n + j];
                }
                float re = cre[i][j] + bre;
                float im = cim[i][j] + bim;
                float mag = sqrtf(re * re + im * im);
                float s = fmaxf(mag + mb, 0.f) / (mag + LN_EPS);
                r[j] = re * s;
                q[j] = im * s;
            }
            const size_t off = (size_t)mloc * N + n;   // static-safe in g_up
            *reinterpret_cast<float4*>(g_up_re + off) =
                make_float4(r[0], r[1], r[2], r[3]);
            *reinterpret_cast<float4*>(g_up_im + off) =
                make_float4(q[0], q[1], q[2], q[3]);
        } else {
#pragma unroll
            for (int j = 0; j < TN; j++) { r[j] = cre[i][j]; q[j] = cim[i][j]; }
            const size_t off = (size_t)mloc * N + n;   // static-safe in g_dn
            *reinterpret_cast<float4*>(g_dn_re + off) =
                make_float4(r[0], r[1], r[2], r[3]);
            *reinterpret_cast<float4*>(g_dn_im + off) =
                make_float4(q[0], q[1], q[2], q[3]);
        }
    }
}

// Complex LayerNorm over D + residual, one block per (chunk-local) token row.
// OUT_MODE 0: real-part-only float32 output (out[g] = real)
// OUT_MODE 1: interleaved complex (out[2g]=re, out[2g+1]=im)
template <int OUT_MODE>
__global__ void __launch_bounds__(256)
ln_res_kernel(const float* __restrict__ xr, const float* __restrict__ xi,
              const float* __restrict__ gr, const float* __restrict__ gi,
              const float* __restrict__ br, const float* __restrict__ bi,
              float* __restrict__ out, int m_base,
              size_t x_lim, size_t p_lim, size_t out_cap) {
    const int m = blockIdx.x;                       // chunk-local row
    const size_t base = (size_t)m * CD;             // into g_dn
    const size_t gbase = (size_t)(m_base + m) * CD; // into x / out
    const int tid = threadIdx.x;
    const bool x_ok = (gbase + CD) <= x_lim;
    const bool p_ok = (size_t)CD <= p_lim;

    float sr = 0.f, si = 0.f, sq = 0.f;
    for (int d = tid; d < CD; d += 256) {
        float r = g_dn_re[base + d];
        float q = g_dn_im[base + d];
        sr += r; si += q; sq += r * r + q * q;
    }
    __shared__ float red0[256], red1[256], red2[256];
    red0[tid] = sr; red1[tid] = si; red2[tid] = sq;
    __syncthreads();
    for (int s = 128; s > 0; s >>= 1) {
        if (tid < s) {
            red0[tid] += red0[tid + s];
            red1[tid] += red1[tid + s];
            red2[tid] += red2[tid + s];
        }
        __syncthreads();
    }
    const float inv_d = 1.f / (float)CD;
    const float mur = red0[0] * inv_d;
    const float mui = red1[0] * inv_d;
    const float var = red2[0] * inv_d - (mur * mur + mui * mui);
    const float rstd = rsqrtf(var + LN_EPS);

    for (int d = tid; d < CD; d += 256) {
        float zr = (g_dn_re[base + d] - mur) * rstd;
        float zi = (g_dn_im[base + d] - mui) * rstd;
        float g_r = p_ok ? gr[d] : 1.f;
        float g_i = p_ok ? gi[d] : 0.f;
        float b_r = p_ok ? br[d] : 0.f;
        float b_i = p_ok ? bi[d] : 0.f;
        float xre = x_ok ? xr[gbase + d] : 0.f;
        float xim = x_ok ? xi[gbase + d] : 0.f;
        float o_r = g_r * zr - g_i * zi + b_r + xre;
        float o_i = g_r * zi + g_i * zr + b_i + xim;
        if (OUT_MODE == 0) {
            const size_t fo = gbase + d;
            if (fo < out_cap) out[fo] = o_r;
        } else {
            const size_t fo = 2 * (gbase + d);
            if (fo + 1 < out_cap) { out[fo] = o_r; out[fo + 1] = o_i; }
        }
    }
}

// ---------------- host-side binding ----------------
static bool match_sig(const int* s, const long long* want, long long scale) {
    for (int i = 0; i < 13; i++)
        if ((long long)s[i] != want[i] * scale) return false;
    return true;
}

extern "C" void kernel_launch(void* const* d_in, const int* in_sizes, int n_in,
                              void* d_out, int out_size) {
    if (n_in < 13) return;
    for (int i = 0; i < 13; i++) if (d_in[i] == nullptr) return;

    static const long long SIG_DICT[13] =
        {16777216,16777216,16777216,16777216,8192,8192,8192,
         16777216,16777216,2048,2048,2048,2048};
    static const long long SIG_ALPHA[13] =
        {16777216,16777216,16777216,16777216,8192,8192,
         2048,2048,2048,2048,8192,16777216,16777216};

    int order = 0;        // 0=dict, 1=alpha
    long long unit = 1;   // element-count divisor
    if (match_sig(in_sizes, SIG_DICT, 1))       { order = 0; unit = 1; }
    else if (match_sig(in_sizes, SIG_ALPHA, 1)) { order = 1; unit = 1; }
    else if (match_sig(in_sizes, SIG_DICT, 4))  { order = 0; unit = 4; }
    else if (match_sig(in_sizes, SIG_ALPHA, 4)) { order = 1; unit = 4; }

    const float *x_re, *x_im, *Wup_re, *Wup_im, *bias_re, *bias_im, *mrb;
    const float *Wd_re, *Wd_im, *g_re, *g_im, *be_re, *be_im;
    size_t sz[13];
    for (int i = 0; i < 13; i++) sz[i] = (size_t)((long long)in_sizes[i] / unit);
    size_t x_lim, wup_lim, wd_lim, bias_lim, ln_lim;

    if (order == 0) {
        x_re   = (const float*)d_in[0];  x_im   = (const float*)d_in[1];
        Wup_re = (const float*)d_in[2];  Wup_im = (const float*)d_in[3];
        bias_re = (const float*)d_in[4]; bias_im = (const float*)d_in[5];
        mrb    = (const float*)d_in[6];
        Wd_re  = (const float*)d_in[7];  Wd_im  = (const float*)d_in[8];
        g_re   = (const float*)d_in[9];  g_im   = (const float*)d_in[10];
        be_re  = (const float*)d_in[11]; be_im  = (const float*)d_in[12];
        x_lim = sz[0] < sz[1] ? sz[0] : sz[1];
        wup_lim = sz[2] < sz[3] ? sz[2] : sz[3];
        bias_lim = sz[4] < sz[5] ? sz[4] : sz[5];
        if (sz[6] < bias_lim) bias_lim = sz[6];
        wd_lim = sz[7] < sz[8] ? sz[7] : sz[8];
        ln_lim = sz[9];
        for (int i = 10; i <= 12; i++) if (sz[i] < ln_lim) ln_lim = sz[i];
    } else {
        Wd_im  = (const float*)d_in[0];  Wd_re  = (const float*)d_in[1];
        Wup_im = (const float*)d_in[2];  Wup_re = (const float*)d_in[3];
        bias_im = (const float*)d_in[4]; bias_re = (const float*)d_in[5];
        be_im  = (const float*)d_in[6];  be_re  = (const float*)d_in[7];
        g_im   = (const float*)d_in[8];  g_re   = (const float*)d_in[9];
        mrb    = (const float*)d_in[10];
        x_im   = (const float*)d_in[11]; x_re   = (const float*)d_in[12];
        wd_lim = sz[0] < sz[1] ? sz[0] : sz[1];
        wup_lim = sz[2] < sz[3] ? sz[2] : sz[3];
        bias_lim = sz[4] < sz[5] ? sz[4] : sz[5];
        if (sz[10] < bias_lim) bias_lim = sz[10];
        ln_lim = sz[6];
        for (int i = 7; i <= 9; i++) if (sz[i] < ln_lim) ln_lim = sz[i];
        x_lim = sz[11] < sz[12] ? sz[11] : sz[12];
    }

    // Output contract switch. out_size == B*S*D exactly => float32 buffer of
    // 16.7M elements holding the REAL PART ONLY (complex64 is not a supported
    // harness output dtype; astype(float32) drops imag). Otherwise treat
    // out_size as the float-element capacity for interleaved complex.
    const bool real_only = ((long long)out_size == 16777216LL);
    const size_t out_cap = (size_t)(long long)out_size;

    for (int c = 0; c < NCHUNKS; c++) {
        const int mb = c * MCHUNK;
        dim3 g1(CF / BN, MCHUNK / BM);
        cgemm_nt<0><<<g1, THREADS>>>(x_re, x_im, Wup_re, Wup_im,
                                     bias_re, bias_im, mrb,
                                     mb, CF, CD,
                                     x_lim, wup_lim, bias_lim);
        dim3 g2(CD / BN, MCHUNK / BM);
        cgemm_nt<1><<<g2, THREADS>>>(nullptr, nullptr, Wd_re, Wd_im,
                                     nullptr, nullptr, nullptr,
                                     mb, CD, CF,
                                     (size_t)MCHUNK * CF, wd_lim, 0);
        if (real_only) {
            ln_res_kernel<0><<<MCHUNK, 256>>>(x_re, x_im, g_re, g_im,
                                              be_re, be_im, (float*)d_out, mb,
                                              x_lim, ln_lim, out_cap);
        } else {
            ln_res_kernel<1><<<MCHUNK, 256>>>(x_re, x_im, g_re, g_im,
                                              be_re, be_im, (float*)d_out, mb,
                                              x_lim, ln_lim, out_cap);
        }
    }
}

// round 7
// speedup vs baseline: 1.6334x; 1.6334x over previous
#include <cuda_runtime.h>
#include <cuda_bf16.h>
#include <math.h>
#include <stdint.h>

#define LN_EPS 1e-5f

// Problem constants
constexpr int CB = 4, CS = 2048, CD = 2048, CF = 8192;
constexpr int CM = CB * CS;      // 8192 tokens
constexpr int MCHUNK = 2048;     // M rows per pipeline chunk
constexpr int NCHUNKS = CM / MCHUNK;

// GEMM tiling
constexpr int BM = 128, BN = 64, BK = 32;
constexpr int WARPS_M = 4, WARPS_N = 2;          // warp grid
constexpr int THREADS = 32 * WARPS_M * WARPS_N;  // 256
constexpr int PW = 20;  // smem pitch in 32-bit words per row (16 data + 4 pad)

// Smem plane offsets (in 32-bit words)
constexpr int A_HI_RE = 0;
constexpr int A_LO_RE = BM * PW;
constexpr int A_HI_IM = 2 * BM * PW;
constexpr int A_LO_IM = 3 * BM * PW;
constexpr int B_HI_RE = 4 * BM * PW;
constexpr int B_LO_RE = B_HI_RE + BN * PW;
constexpr int B_HI_IM = B_HI_RE + 2 * BN * PW;
constexpr int B_LO_IM = B_HI_RE + 3 * BN * PW;
constexpr int SMEM_WORDS = 4 * BM * PW + 4 * BN * PW;   // 15360
constexpr int SMEM_BYTES = SMEM_WORDS * 4;              // 61440

// Scratch (device globals)
__device__ __align__(16) float g_up_re[(size_t)MCHUNK * CF];
__device__ __align__(16) float g_up_im[(size_t)MCHUNK * CF];
__device__ __align__(16) float g_dn_re[(size_t)MCHUNK * CD];
__device__ __align__(16) float g_dn_im[(size_t)MCHUNK * CD];

__device__ __forceinline__ float4 ld4_guard(const float* p, size_t off, size_t lim) {
    if (off + 4 <= lim) return *reinterpret_cast<const float4*>(p + off);
    float4 z; z.x = z.y = z.z = z.w = 0.f;
    return z;
}

// Split two fp32 into packed bf16 hi / lo words (k-ascending: first elem = low half)
__device__ __forceinline__ void split2(float x, float y, uint32_t& hi, uint32_t& lo) {
    __nv_bfloat16 xh = __float2bfloat16_rn(x);
    __nv_bfloat16 yh = __float2bfloat16_rn(y);
    float xr = x - __bfloat162float(xh);
    float yr = y - __bfloat162float(yh);
    __nv_bfloat16 xl = __float2bfloat16_rn(xr);
    __nv_bfloat16 yl = __float2bfloat16_rn(yr);
    hi = (uint32_t)__bfloat16_as_ushort(xh) |
         ((uint32_t)__bfloat16_as_ushort(yh) << 16);
    lo = (uint32_t)__bfloat16_as_ushort(xl) |
         ((uint32_t)__bfloat16_as_ushort(yl) << 16);
}

__device__ __forceinline__ void mma16816(float* c, const uint32_t* a, const uint32_t* b) {
    asm volatile(
        "mma.sync.aligned.m16n8k16.row.col.f32.bf16.bf16.f32 "
        "{%0,%1,%2,%3}, {%4,%5,%6,%7}, {%8,%9}, {%0,%1,%2,%3};\n"
        : "+f"(c[0]), "+f"(c[1]), "+f"(c[2]), "+f"(c[3])
        : "r"(a[0]), "r"(a[1]), "r"(a[2]), "r"(a[3]), "r"(b[0]), "r"(b[1]));
}

// Complex NT GEMM via split-bf16 tensor cores.
// C[m,n] = sum_k A[m,k]*B[n,k] (complex). A,B planar fp32, K-contiguous.
// PHASE 0: A = inputs (rows m_base+..), C = g_up (chunk-local), bias+modrelu epi.
// PHASE 1: A = g_up (chunk-local), C = g_dn (chunk-local), plain store.
template <int PHASE>
__global__ void __launch_bounds__(THREADS)
cgemm_nt(const float* __restrict__ Are, const float* __restrict__ Aim,
         const float* __restrict__ Bre, const float* __restrict__ Bim,
         const float* __restrict__ bias_re, const float* __restrict__ bias_im,
         const float* __restrict__ mrb,
         int m_base, int N, int K,
         size_t a_lim, size_t b_lim, size_t bias_lim) {
    extern __shared__ uint32_t s[];

    const int tid = threadIdx.x;
    const int lane = tid & 31;
    const int warp = tid >> 5;
    const int wm = warp >> 1;         // 0..3
    const int wn = warp & 1;          // 0..1
    const int g  = lane >> 2;         // 0..7
    const int tg = lane & 3;          // 0..3
    const int m0 = blockIdx.y * BM;   // chunk-local row base
    const int n0 = blockIdx.x * BN;

    const float* Ar = (PHASE == 0) ? Are : g_up_re;
    const float* Ai = (PHASE == 0) ? Aim : g_up_im;
    const size_t a_row0 = (PHASE == 0) ? (size_t)m_base : 0;

    const bool a_ok = (a_row0 + m0 + BM) * (size_t)K <= a_lim;
    const bool b_ok = ((size_t)n0 + BN) * (size_t)K <= b_lim;

    float accRe[2][4][4];   // [mi][ni][frag]
    float accIm[2][4][4];
#pragma unroll
    for (int mi = 0; mi < 2; mi++)
#pragma unroll
        for (int ni = 0; ni < 4; ni++)
#pragma unroll
            for (int r = 0; r < 4; r++) { accRe[mi][ni][r] = 0.f; accIm[mi][ni][r] = 0.f; }

    for (int k0 = 0; k0 < K; k0 += BK) {
        // ---- load + split A tile: BM x BK fp32 (re,im) => 1024 float4/plane
#pragma unroll
        for (int t = 0; t < 4; t++) {
            int idx = tid + t * THREADS;          // 0..1023
            int row = idx >> 3;
            int q = idx & 7;                      // float4 index in row
            const size_t off = (a_row0 + m0 + row) * (size_t)K + k0 + q * 4;
            float4 vr, vi;
            if (a_ok) {
                vr = *reinterpret_cast<const float4*>(Ar + off);
                vi = *reinterpret_cast<const float4*>(Ai + off);
            } else {
                vr = ld4_guard(Ar, off, a_lim);
                vi = ld4_guard(Ai, off, a_lim);
            }
            const int wi = row * PW + q * 2;
            split2(vr.x, vr.y, s[A_HI_RE + wi],     s[A_LO_RE + wi]);
            split2(vr.z, vr.w, s[A_HI_RE + wi + 1], s[A_LO_RE + wi + 1]);
            split2(vi.x, vi.y, s[A_HI_IM + wi],     s[A_LO_IM + wi]);
            split2(vi.z, vi.w, s[A_HI_IM + wi + 1], s[A_LO_IM + wi + 1]);
        }
        // ---- load + split B tile: BN x BK => 512 float4/plane
#pragma unroll
        for (int t = 0; t < 2; t++) {
            int idx = tid + t * THREADS;          // 0..511
            int row = idx >> 3;
            int q = idx & 7;
            const size_t off = (size_t)(n0 + row) * K + k0 + q * 4;
            float4 vr, vi;
            if (b_ok) {
                vr = *reinterpret_cast<const float4*>(Bre + off);
                vi = *reinterpret_cast<const float4*>(Bim + off);
            } else {
                vr = ld4_guard(Bre, off, b_lim);
                vi = ld4_guard(Bim, off, b_lim);
            }
            const int wi = row * PW + q * 2;
            split2(vr.x, vr.y, s[B_HI_RE + wi],     s[B_LO_RE + wi]);
            split2(vr.z, vr.w, s[B_HI_RE + wi + 1], s[B_LO_RE + wi + 1]);
            split2(vi.x, vi.y, s[B_HI_IM + wi],     s[B_LO_IM + wi]);
            split2(vi.z, vi.w, s[B_HI_IM + wi + 1], s[B_LO_IM + wi + 1]);
        }
        __syncthreads();

        // ---- MMA over 2 k16 halves
#pragma unroll
        for (int ks = 0; ks < 2; ks++) {
            const int kb = ks * 8 + tg;

            // B fragments: rows = n index (Bs stored [n][k])
            uint32_t Brh[4][2], Brl[4][2], Bih[4][2], Bil[4][2];
#pragma unroll
            for (int ni = 0; ni < 4; ni++) {
                const int rb = (wn * 32 + ni * 8 + g) * PW;
                Brh[ni][0] = s[B_HI_RE + rb + kb];     Brh[ni][1] = s[B_HI_RE + rb + kb + 4];
                Brl[ni][0] = s[B_LO_RE + rb + kb];     Brl[ni][1] = s[B_LO_RE + rb + kb + 4];
                Bih[ni][0] = s[B_HI_IM + rb + kb];     Bih[ni][1] = s[B_HI_IM + rb + kb + 4];
                Bil[ni][0] = s[B_LO_IM + rb + kb];     Bil[ni][1] = s[B_LO_IM + rb + kb + 4];
            }
            // A fragments
            uint32_t Arh[2][4], Arl[2][4], Aih[2][4], Ail[2][4], nAih[2][4], nAil[2][4];
#pragma unroll
            for (int mi = 0; mi < 2; mi++) {
                const int r0 = (wm * 32 + mi * 16 + g) * PW;
                const int r1 = r0 + 8 * PW;
                Arh[mi][0] = s[A_HI_RE + r0 + kb];     Arh[mi][1] = s[A_HI_RE + r1 + kb];
                Arh[mi][2] = s[A_HI_RE + r0 + kb + 4]; Arh[mi][3] = s[A_HI_RE + r1 + kb + 4];
                Arl[mi][0] = s[A_LO_RE + r0 + kb];     Arl[mi][1] = s[A_LO_RE + r1 + kb];
                Arl[mi][2] = s[A_LO_RE + r0 + kb + 4]; Arl[mi][3] = s[A_LO_RE + r1 + kb + 4];
                Aih[mi][0] = s[A_HI_IM + r0 + kb];     Aih[mi][1] = s[A_HI_IM + r1 + kb];
                Aih[mi][2] = s[A_HI_IM + r0 + kb + 4]; Aih[mi][3] = s[A_HI_IM + r1 + kb + 4];
                Ail[mi][0] = s[A_LO_IM + r0 + kb];     Ail[mi][1] = s[A_LO_IM + r1 + kb];
                Ail[mi][2] = s[A_LO_IM + r0 + kb + 4]; Ail[mi][3] = s[A_LO_IM + r1 + kb + 4];
#pragma unroll
                for (int r = 0; r < 4; r++) {
                    nAih[mi][r] = Aih[mi][r] ^ 0x80008000u;
                    nAil[mi][r] = Ail[mi][r] ^ 0x80008000u;
                }
            }
#pragma unroll
            for (int mi = 0; mi < 2; mi++) {
#pragma unroll
                for (int ni = 0; ni < 4; ni++) {
                    // cre = ar*br - ai*bi  (split: hh + hl + lh)
                    mma16816(accRe[mi][ni], Arh[mi],  Brh[ni]);
                    mma16816(accRe[mi][ni], Arh[mi],  Brl[ni]);
                    mma16816(accRe[mi][ni], Arl[mi],  Brh[ni]);
                    mma16816(accRe[mi][ni], nAih[mi], Bih[ni]);
                    mma16816(accRe[mi][ni], nAih[mi], Bil[ni]);
                    mma16816(accRe[mi][ni], nAil[mi], Bih[ni]);
                    // cim = ar*bi + ai*br
                    mma16816(accIm[mi][ni], Arh[mi],  Bih[ni]);
                    mma16816(accIm[mi][ni], Arh[mi],  Bil[ni]);
                    mma16816(accIm[mi][ni], Arl[mi],  Bih[ni]);
                    mma16816(accIm[mi][ni], Aih[mi],  Brh[ni]);
                    mma16816(accIm[mi][ni], Aih[mi],  Brl[ni]);
                    mma16816(accIm[mi][ni], Ail[mi],  Brh[ni]);
                }
            }
        }
        __syncthreads();
    }

    // ---- epilogue ----
    const bool bias_ok = (PHASE != 0) || ((size_t)n0 + BN <= bias_lim);
#pragma unroll
    for (int mi = 0; mi < 2; mi++) {
#pragma unroll
        for (int ni = 0; ni < 4; ni++) {
            const int col = n0 + wn * 32 + ni * 8 + 2 * tg;
#pragma unroll
            for (int h = 0; h < 2; h++) {           // h=0: rows g, h=1: rows g+8
                const int row = m0 + wm * 32 + mi * 16 + g + h * 8;
                float re0 = accRe[mi][ni][2 * h], re1 = accRe[mi][ni][2 * h + 1];
                float im0 = accIm[mi][ni][2 * h], im1 = accIm[mi][ni][2 * h + 1];
                if (PHASE == 0) {
                    float br0 = 0.f, br1 = 0.f, bi0 = 0.f, bi1 = 0.f, mb0 = 0.f, mb1 = 0.f;
                    if (bias_ok) {
                        br0 = bias_re[col]; br1 = bias_re[col + 1];
                        bi0 = bias_im[col]; bi1 = bias_im[col + 1];
                        mb0 = mrb[col];     mb1 = mrb[col + 1];
                    }
                    re0 += br0; im0 += bi0; re1 += br1; im1 += bi1;
                    float mag0 = sqrtf(re0 * re0 + im0 * im0);
                    float mag1 = sqrtf(re1 * re1 + im1 * im1);
                    float s0 = fmaxf(mag0 + mb0, 0.f) / (mag0 + LN_EPS);
                    float s1 = fmaxf(mag1 + mb1, 0.f) / (mag1 + LN_EPS);
                    re0 *= s0; im0 *= s0; re1 *= s1; im1 *= s1;
                    const size_t off = (size_t)row * N + col;
                    *reinterpret_cast<float2*>(g_up_re + off) = make_float2(re0, re1);
                    *reinterpret_cast<float2*>(g_up_im + off) = make_float2(im0, im1);
                } else {
                    const size_t off = (size_t)row * N + col;
                    *reinterpret_cast<float2*>(g_dn_re + off) = make_float2(re0, re1);
                    *reinterpret_cast<float2*>(g_dn_im + off) = make_float2(im0, im1);
                }
            }
        }
    }
}

// Complex LayerNorm over D + residual, one block per (chunk-local) token row.
// OUT_MODE 0: real-only float32 out; OUT_MODE 1: interleaved complex.
template <int OUT_MODE>
__global__ void __launch_bounds__(256)
ln_res_kernel(const float* __restrict__ xr, const float* __restrict__ xi,
              const float* __restrict__ gr, const float* __restrict__ gi,
              const float* __restrict__ br, const float* __restrict__ bi,
              float* __restrict__ out, int m_base,
              size_t x_lim, size_t p_lim, size_t out_cap) {
    const int m = blockIdx.x;
    const size_t base = (size_t)m * CD;
    const size_t gbase = (size_t)(m_base + m) * CD;
    const int tid = threadIdx.x;
    const bool x_ok = (gbase + CD) <= x_lim;
    const bool p_ok = (size_t)CD <= p_lim;

    float sr = 0.f, si = 0.f, sq = 0.f;
    for (int d = tid; d < CD; d += 256) {
        float r = g_dn_re[base + d];
        float q = g_dn_im[base + d];
        sr += r; si += q; sq += r * r + q * q;
    }
    __shared__ float red0[256], red1[256], red2[256];
    red0[tid] = sr; red1[tid] = si; red2[tid] = sq;
    __syncthreads();
    for (int st = 128; st > 0; st >>= 1) {
        if (tid < st) {
            red0[tid] += red0[tid + st];
            red1[tid] += red1[tid + st];
            red2[tid] += red2[tid + st];
        }
        __syncthreads();
    }
    const float inv_d = 1.f / (float)CD;
    const float mur = red0[0] * inv_d;
    const float mui = red1[0] * inv_d;
    const float var = red2[0] * inv_d - (mur * mur + mui * mui);
    const float rstd = rsqrtf(var + LN_EPS);

    for (int d = tid; d < CD; d += 256) {
        float zr = (g_dn_re[base + d] - mur) * rstd;
        float zi = (g_dn_im[base + d] - mui) * rstd;
        float g_r = p_ok ? gr[d] : 1.f;
        float g_i = p_ok ? gi[d] : 0.f;
        float b_r = p_ok ? br[d] : 0.f;
        float b_i = p_ok ? bi[d] : 0.f;
        float xre = x_ok ? xr[gbase + d] : 0.f;
        float xim = x_ok ? xi[gbase + d] : 0.f;
        float o_r = g_r * zr - g_i * zi + b_r + xre;
        float o_i = g_r * zi + g_i * zr + b_i + xim;
        if (OUT_MODE == 0) {
            const size_t fo = gbase + d;
            if (fo < out_cap) out[fo] = o_r;
        } else {
            const size_t fo = 2 * (gbase + d);
            if (fo + 1 < out_cap) { out[fo] = o_r; out[fo + 1] = o_i; }
        }
    }
}

// ---------------- host-side binding ----------------
static bool match_sig(const int* s, const long long* want, long long scale) {
    for (int i = 0; i < 13; i++)
        if ((long long)s[i] != want[i] * scale) return false;
    return true;
}

extern "C" void kernel_launch(void* const* d_in, const int* in_sizes, int n_in,
                              void* d_out, int out_size) {
    if (n_in < 13) return;
    for (int i = 0; i < 13; i++) if (d_in[i] == nullptr) return;

    static const long long SIG_DICT[13] =
        {16777216,16777216,16777216,16777216,8192,8192,8192,
         16777216,16777216,2048,2048,2048,2048};
    static const long long SIG_ALPHA[13] =
        {16777216,16777216,16777216,16777216,8192,8192,
         2048,2048,2048,2048,8192,16777216,16777216};

    int order = 0;
    long long unit = 1;
    if (match_sig(in_sizes, SIG_DICT, 1))       { order = 0; unit = 1; }
    else if (match_sig(in_sizes, SIG_ALPHA, 1)) { order = 1; unit = 1; }
    else if (match_sig(in_sizes, SIG_DICT, 4))  { order = 0; unit = 4; }
    else if (match_sig(in_sizes, SIG_ALPHA, 4)) { order = 1; unit = 4; }

    const float *x_re, *x_im, *Wup_re, *Wup_im, *bias_re, *bias_im, *mrb;
    const float *Wd_re, *Wd_im, *g_re, *g_im, *be_re, *be_im;
    size_t sz[13];
    for (int i = 0; i < 13; i++) sz[i] = (size_t)((long long)in_sizes[i] / unit);
    size_t x_lim, wup_lim, wd_lim, bias_lim, ln_lim;

    if (order == 0) {
        x_re   = (const float*)d_in[0];  x_im   = (const float*)d_in[1];
        Wup_re = (const float*)d_in[2];  Wup_im = (const float*)d_in[3];
        bias_re = (const float*)d_in[4]; bias_im = (const float*)d_in[5];
        mrb    = (const float*)d_in[6];
        Wd_re  = (const float*)d_in[7];  Wd_im  = (const float*)d_in[8];
        g_re   = (const float*)d_in[9];  g_im   = (const float*)d_in[10];
        be_re  = (const float*)d_in[11]; be_im  = (const float*)d_in[12];
        x_lim = sz[0] < sz[1] ? sz[0] : sz[1];
        wup_lim = sz[2] < sz[3] ? sz[2] : sz[3];
        bias_lim = sz[4] < sz[5] ? sz[4] : sz[5];
        if (sz[6] < bias_lim) bias_lim = sz[6];
        wd_lim = sz[7] < sz[8] ? sz[7] : sz[8];
        ln_lim = sz[9];
        for (int i = 10; i <= 12; i++) if (sz[i] < ln_lim) ln_lim = sz[i];
    } else {
        Wd_im  = (const float*)d_in[0];  Wd_re  = (const float*)d_in[1];
        Wup_im = (const float*)d_in[2];  Wup_re = (const float*)d_in[3];
        bias_im = (const float*)d_in[4]; bias_re = (const float*)d_in[5];
        be_im  = (const float*)d_in[6];  be_re  = (const float*)d_in[7];
        g_im   = (const float*)d_in[8];  g_re   = (const float*)d_in[9];
        mrb    = (const float*)d_in[10];
        x_im   = (const float*)d_in[11]; x_re   = (const float*)d_in[12];
        wd_lim = sz[0] < sz[1] ? sz[0] : sz[1];
        wup_lim = sz[2] < sz[3] ? sz[2] : sz[3];
        bias_lim = sz[4] < sz[5] ? sz[4] : sz[5];
        if (sz[10] < bias_lim) bias_lim = sz[10];
        ln_lim = sz[6];
        for (int i = 7; i <= 9; i++) if (sz[i] < ln_lim) ln_lim = sz[i];
        x_lim = sz[11] < sz[12] ? sz[11] : sz[12];
    }

    const bool real_only = ((long long)out_size == 16777216LL);
    const size_t out_cap = (size_t)(long long)out_size;

    // Opt-in to 60KB dynamic smem (host-side attr set; not a stream op)
    static bool attr_done = false;
    if (!attr_done) {
        cudaFuncSetAttribute(cgemm_nt<0>, cudaFuncAttributeMaxDynamicSharedMemorySize, SMEM_BYTES);
        cudaFuncSetAttribute(cgemm_nt<1>, cudaFuncAttributeMaxDynamicSharedMemorySize, SMEM_BYTES);
        attr_done = true;
    }

    for (int c = 0; c < NCHUNKS; c++) {
        const int mb = c * MCHUNK;
        dim3 g1(CF / BN, MCHUNK / BM);
        cgemm_nt<0><<<g1, THREADS, SMEM_BYTES>>>(x_re, x_im, Wup_re, Wup_im,
                                                 bias_re, bias_im, mrb,
                                                 mb, CF, CD,
                                                 x_lim, wup_lim, bias_lim);
        dim3 g2(CD / BN, MCHUNK / BM);
        cgemm_nt<1><<<g2, THREADS, SMEM_BYTES>>>(nullptr, nullptr, Wd_re, Wd_im,
                                                 nullptr, nullptr, nullptr,
                                                 mb, CD, CF,
                                                 (size_t)MCHUNK * CF, wd_lim, 0);
        if (real_only) {
            ln_res_kernel<0><<<MCHUNK, 256>>>(x_re, x_im, g_re, g_im,
                                              be_re, be_im, (float*)d_out, mb,
                                              x_lim, ln_lim, out_cap);
        } else {
            ln_res_kernel<1><<<MCHUNK, 256>>>(x_re, x_im, g_re, g_im,
                                              be_re, be_im, (float*)d_out, mb,
                                              x_lim, ln_lim, out_cap);
        }
    }
}

// round 8
// speedup vs baseline: 2.9791x; 1.8239x over previous
#include <cuda_runtime.h>
#include <cuda_bf16.h>
#include <math.h>
#include <stdint.h>

#define LN_EPS 1e-5f

// Problem constants
constexpr int CB = 4, CS = 2048, CD = 2048, CF = 8192;
constexpr int CM = CB * CS;      // 8192 tokens
constexpr int MCHUNK = 2048;
constexpr int NCHUNKS = CM / MCHUNK;

// GEMM tiling
constexpr int BM = 128, BN = 64, BK = 32;
constexpr int THREADS = 256;     // 8 warps: 4 (M) x 2 (N)
constexpr int PW = 20;           // smem row pitch in words (16 data + 4 pad)
constexpr int KW = BK / 2;       // 16 data words per row

// Smem layout (words): per stage, 4 A planes then 4 B planes.
constexpr int A_PL = BM * PW;               // 2560 words per A plane
constexpr int B_PL = BN * PW;               // 1280 words per B plane
constexpr int B_OFF = 4 * A_PL;             // 10240
constexpr int STAGE_W = 4 * A_PL + 4 * B_PL; // 15360 words
constexpr int SMEM_BYTES = 2 * STAGE_W * 4;  // 122880 B

// ---- device-global scratch: packed bf16x2 hi/lo planes (word = k,k+1) ----
constexpr size_t XW  = (size_t)CM * CD / 2;      // 8.39M words
constexpr size_t WW  = (size_t)CF * CD / 2;      // 8.39M
constexpr size_t UW  = (size_t)MCHUNK * CF / 2;  // 8.39M
__device__ __align__(16) uint32_t g_cX_hr[XW], g_cX_lr[XW], g_cX_hi[XW], g_cX_li[XW];
__device__ __align__(16) uint32_t g_cWu_hr[WW], g_cWu_lr[WW], g_cWu_hi[WW], g_cWu_li[WW];
__device__ __align__(16) uint32_t g_cWd_hr[WW], g_cWd_lr[WW], g_cWd_hi[WW], g_cWd_li[WW];
__device__ __align__(16) uint32_t g_cUp_hr[UW], g_cUp_lr[UW], g_cUp_hi[UW], g_cUp_li[UW];
__device__ __align__(16) float g_dn_re[(size_t)MCHUNK * CD];
__device__ __align__(16) float g_dn_im[(size_t)MCHUNK * CD];

// Split two fp32 into packed bf16 hi / lo words (low element = low half)
__device__ __forceinline__ void split2(float x, float y, uint32_t& hi, uint32_t& lo) {
    __nv_bfloat16 xh = __float2bfloat16_rn(x);
    __nv_bfloat16 yh = __float2bfloat16_rn(y);
    float xr = x - __bfloat162float(xh);
    float yr = y - __bfloat162float(yh);
    __nv_bfloat16 xl = __float2bfloat16_rn(xr);
    __nv_bfloat16 yl = __float2bfloat16_rn(yr);
    hi = (uint32_t)__bfloat16_as_ushort(xh) | ((uint32_t)__bfloat16_as_ushort(yh) << 16);
    lo = (uint32_t)__bfloat16_as_ushort(xl) | ((uint32_t)__bfloat16_as_ushort(yl) << 16);
}

__device__ __forceinline__ void mma16816(float* c, const uint32_t* a, const uint32_t* b) {
    asm volatile(
        "mma.sync.aligned.m16n8k16.row.col.f32.bf16.bf16.f32 "
        "{%0,%1,%2,%3}, {%4,%5,%6,%7}, {%8,%9}, {%0,%1,%2,%3};\n"
        : "+f"(c[0]), "+f"(c[1]), "+f"(c[2]), "+f"(c[3])
        : "r"(a[0]), "r"(a[1]), "r"(a[2]), "r"(a[3]), "r"(b[0]), "r"(b[1]));
}

__device__ __forceinline__ void cpasync16(uint32_t smem_bytes_addr, const void* g) {
    asm volatile("cp.async.cg.shared.global [%0], [%1], 16;\n"
                 :: "r"(smem_bytes_addr), "l"(g));
}
#define CP_COMMIT() asm volatile("cp.async.commit_group;\n")
template <int N>
__device__ __forceinline__ void cp_wait() {
    asm volatile("cp.async.wait_group %0;\n" :: "n"(N));
}

// Pre-conversion: fp32 planar -> packed bf16x2 hi/lo planes. One word/thread.
__global__ void __launch_bounds__(256)
conv_kernel(const float* __restrict__ re, const float* __restrict__ im,
            uint32_t* __restrict__ hr, uint32_t* __restrict__ lr,
            uint32_t* __restrict__ hi_, uint32_t* __restrict__ li,
            size_t nwords, size_t lim) {
    size_t i = (size_t)blockIdx.x * 256 + threadIdx.x;
    if (i >= nwords) return;
    size_t e = 2 * i;
    float r0 = 0.f, r1 = 0.f, q0 = 0.f, q1 = 0.f;
    if (e + 2 <= lim) {
        float2 v = *reinterpret_cast<const float2*>(re + e);
        float2 w = *reinterpret_cast<const float2*>(im + e);
        r0 = v.x; r1 = v.y; q0 = w.x; q1 = w.y;
    }
    split2(r0, r1, hr[i], lr[i]);
    split2(q0, q1, hi_[i], li[i]);
}

// Complex NT GEMM, pre-converted bf16 operands, cp.async double buffering.
// PHASE 0: A = g_cX (rows m_base+..), B = g_cWu, epi = bias+modrelu -> g_cUp (bf16)
// PHASE 1: A = g_cUp (chunk-local), B = g_cWd, epi = plain -> g_dn (fp32)
template <int PHASE>
__global__ void __launch_bounds__(THREADS)
cgemm_nt(const float* __restrict__ bias_re, const float* __restrict__ bias_im,
         const float* __restrict__ mrb,
         int m_base, int N, int K, size_t bias_lim) {
    extern __shared__ uint32_t s[];
    const uint32_t smem_b = (uint32_t)__cvta_generic_to_shared(s);

    const int tid = threadIdx.x;
    const int lane = tid & 31;
    const int warp = tid >> 5;
    const int wm = warp >> 1;
    const int wn = warp & 1;
    const int g  = lane >> 2;
    const int tg = lane & 3;
    const int m0 = blockIdx.y * BM;
    const int n0 = blockIdx.x * BN;

    const uint32_t* Apl[4];
    const uint32_t* Bpl[4];
    int a_row0;
    if (PHASE == 0) {
        Apl[0] = g_cX_hr; Apl[1] = g_cX_lr; Apl[2] = g_cX_hi; Apl[3] = g_cX_li;
        Bpl[0] = g_cWu_hr; Bpl[1] = g_cWu_lr; Bpl[2] = g_cWu_hi; Bpl[3] = g_cWu_li;
        a_row0 = m_base;
    } else {
        Apl[0] = g_cUp_hr; Apl[1] = g_cUp_lr; Apl[2] = g_cUp_hi; Apl[3] = g_cUp_li;
        Bpl[0] = g_cWd_hr; Bpl[1] = g_cWd_lr; Bpl[2] = g_cWd_hi; Bpl[3] = g_cWd_li;
        a_row0 = 0;
    }
    const int rw = K / 2;  // row length in words

    float accRe[2][4][4], accIm[2][4][4];
#pragma unroll
    for (int mi = 0; mi < 2; mi++)
#pragma unroll
        for (int ni = 0; ni < 4; ni++)
#pragma unroll
            for (int r = 0; r < 4; r++) { accRe[mi][ni][r] = 0.f; accIm[mi][ni][r] = 0.f; }

    // Stage loader: 8 A chunks + 4 B chunks per thread, 16B each.
    auto load_stage = [&](int buf, int k0) {
        const int kw0 = k0 >> 1;
        const uint32_t sb = smem_b + (uint32_t)buf * STAGE_W * 4;
#pragma unroll
        for (int t = 0; t < 8; t++) {
            int c = tid + t * THREADS;      // 0..2047
            int p = c >> 9;
            int r = (c & 511) >> 2;
            int q = c & 3;
            const uint32_t* src = Apl[p] + (size_t)(a_row0 + m0 + r) * rw + kw0 + q * 4;
            uint32_t dst = sb + (uint32_t)(p * A_PL + r * PW + q * 4) * 4;
            cpasync16(dst, src);
        }
#pragma unroll
        for (int t = 0; t < 4; t++) {
            int c = tid + t * THREADS;      // 0..1023
            int p = c >> 8;
            int r = (c & 255) >> 2;
            int q = c & 3;
            const uint32_t* src = Bpl[p] + (size_t)(n0 + r) * rw + kw0 + q * 4;
            uint32_t dst = sb + (uint32_t)(B_OFF + p * B_PL + r * PW + q * 4) * 4;
            cpasync16(dst, src);
        }
        CP_COMMIT();
    };

    const int NK = K / BK;
    load_stage(0, 0);

    for (int it = 0; it < NK; it++) {
        if (it + 1 < NK) {
            load_stage((it + 1) & 1, (it + 1) * BK);
            cp_wait<1>();
        } else {
            cp_wait<0>();
        }
        __syncthreads();

        const int st = (it & 1) * STAGE_W;
        const int AHR = st, ALR = st + A_PL, AHI = st + 2 * A_PL, ALI = st + 3 * A_PL;
        const int BHR = st + B_OFF, BLR = BHR + B_PL, BHI = BHR + 2 * B_PL, BLI = BHR + 3 * B_PL;

#pragma unroll
        for (int ks = 0; ks < 2; ks++) {
            const int kb = ks * 8 + tg;

            uint32_t Brh[4][2], Brl[4][2], Bih[4][2], Bil[4][2];
#pragma unroll
            for (int ni = 0; ni < 4; ni++) {
                const int rb = (wn * 32 + ni * 8 + g) * PW;
                Brh[ni][0] = s[BHR + rb + kb];     Brh[ni][1] = s[BHR + rb + kb + 4];
                Brl[ni][0] = s[BLR + rb + kb];     Brl[ni][1] = s[BLR + rb + kb + 4];
                Bih[ni][0] = s[BHI + rb + kb];     Bih[ni][1] = s[BHI + rb + kb + 4];
                Bil[ni][0] = s[BLI + rb + kb];     Bil[ni][1] = s[BLI + rb + kb + 4];
            }
            uint32_t Arh[2][4], Arl[2][4], Aih[2][4], Ail[2][4], nAih[2][4], nAil[2][4];
#pragma unroll
            for (int mi = 0; mi < 2; mi++) {
                const int r0 = (wm * 32 + mi * 16 + g) * PW;
                const int r1 = r0 + 8 * PW;
                Arh[mi][0] = s[AHR + r0 + kb];     Arh[mi][1] = s[AHR + r1 + kb];
                Arh[mi][2] = s[AHR + r0 + kb + 4]; Arh[mi][3] = s[AHR + r1 + kb + 4];
                Arl[mi][0] = s[ALR + r0 + kb];     Arl[mi][1] = s[ALR + r1 + kb];
                Arl[mi][2] = s[ALR + r0 + kb + 4]; Arl[mi][3] = s[ALR + r1 + kb + 4];
                Aih[mi][0] = s[AHI + r0 + kb];     Aih[mi][1] = s[AHI + r1 + kb];
                Aih[mi][2] = s[AHI + r0 + kb + 4]; Aih[mi][3] = s[AHI + r1 + kb + 4];
                Ail[mi][0] = s[ALI + r0 + kb];     Ail[mi][1] = s[ALI + r1 + kb];
                Ail[mi][2] = s[ALI + r0 + kb + 4]; Ail[mi][3] = s[ALI + r1 + kb + 4];
#pragma unroll
                for (int r = 0; r < 4; r++) {
                    nAih[mi][r] = Aih[mi][r] ^ 0x80008000u;
                    nAil[mi][r] = Ail[mi][r] ^ 0x80008000u;
                }
            }
#pragma unroll
            for (int mi = 0; mi < 2; mi++) {
#pragma unroll
                for (int ni = 0; ni < 4; ni++) {
                    mma16816(accRe[mi][ni], Arh[mi],  Brh[ni]);
                    mma16816(accRe[mi][ni], Arh[mi],  Brl[ni]);
                    mma16816(accRe[mi][ni], Arl[mi],  Brh[ni]);
                    mma16816(accRe[mi][ni], nAih[mi], Bih[ni]);
                    mma16816(accRe[mi][ni], nAih[mi], Bil[ni]);
                    mma16816(accRe[mi][ni], nAil[mi], Bih[ni]);
                    mma16816(accIm[mi][ni], Arh[mi],  Bih[ni]);
                    mma16816(accIm[mi][ni], Arh[mi],  Bil[ni]);
                    mma16816(accIm[mi][ni], Arl[mi],  Bih[ni]);
                    mma16816(accIm[mi][ni], Aih[mi],  Brh[ni]);
                    mma16816(accIm[mi][ni], Aih[mi],  Brl[ni]);
                    mma16816(accIm[mi][ni], Ail[mi],  Brh[ni]);
                }
            }
        }
        __syncthreads();
    }

    // ---- epilogue ----
    const bool bias_ok = (PHASE != 0) || ((size_t)n0 + BN <= bias_lim);
#pragma unroll
    for (int mi = 0; mi < 2; mi++) {
#pragma unroll
        for (int ni = 0; ni < 4; ni++) {
            const int col = n0 + wn * 32 + ni * 8 + 2 * tg;   // even
#pragma unroll
            for (int h = 0; h < 2; h++) {
                const int row = m0 + wm * 32 + mi * 16 + g + h * 8;
                float re0 = accRe[mi][ni][2 * h], re1 = accRe[mi][ni][2 * h + 1];
                float im0 = accIm[mi][ni][2 * h], im1 = accIm[mi][ni][2 * h + 1];
                if (PHASE == 0) {
                    float br0 = 0.f, br1 = 0.f, bi0 = 0.f, bi1 = 0.f, mb0 = 0.f, mb1 = 0.f;
                    if (bias_ok) {
                        br0 = bias_re[col]; br1 = bias_re[col + 1];
                        bi0 = bias_im[col]; bi1 = bias_im[col + 1];
                        mb0 = mrb[col];     mb1 = mrb[col + 1];
                    }
                    re0 += br0; im0 += bi0; re1 += br1; im1 += bi1;
                    float mag0 = sqrtf(re0 * re0 + im0 * im0);
                    float mag1 = sqrtf(re1 * re1 + im1 * im1);
                    float s0 = fmaxf(mag0 + mb0, 0.f) / (mag0 + LN_EPS);
                    float s1 = fmaxf(mag1 + mb1, 0.f) / (mag1 + LN_EPS);
                    re0 *= s0; im0 *= s0; re1 *= s1; im1 *= s1;
                    // split & store packed bf16x2 word directly (k = col, col+1)
                    const size_t wo = (size_t)row * (N / 2) + (col >> 1);
                    split2(re0, re1, g_cUp_hr[wo], g_cUp_lr[wo]);
                    split2(im0, im1, g_cUp_hi[wo], g_cUp_li[wo]);
                } else {
                    const size_t off = (size_t)row * N + col;
                    *reinterpret_cast<float2*>(g_dn_re + off) = make_float2(re0, re1);
                    *reinterpret_cast<float2*>(g_dn_im + off) = make_float2(im0, im1);
                }
            }
        }
    }
}

// Complex LayerNorm over D + residual, one block per (chunk-local) token row.
template <int OUT_MODE>
__global__ void __launch_bounds__(256)
ln_res_kernel(const float* __restrict__ xr, const float* __restrict__ xi,
              const float* __restrict__ gr, const float* __restrict__ gi,
              const float* __restrict__ br, const float* __restrict__ bi,
              float* __restrict__ out, int m_base,
              size_t x_lim, size_t p_lim, size_t out_cap) {
    const int m = blockIdx.x;
    const size_t base = (size_t)m * CD;
    const size_t gbase = (size_t)(m_base + m) * CD;
    const int tid = threadIdx.x;
    const bool x_ok = (gbase + CD) <= x_lim;
    const bool p_ok = (size_t)CD <= p_lim;

    float sr = 0.f, si = 0.f, sq = 0.f;
    for (int d = tid; d < CD; d += 256) {
        float r = g_dn_re[base + d];
        float q = g_dn_im[base + d];
        sr += r; si += q; sq += r * r + q * q;
    }
    __shared__ float red0[256], red1[256], red2[256];
    red0[tid] = sr; red1[tid] = si; red2[tid] = sq;
    __syncthreads();
    for (int st = 128; st > 0; st >>= 1) {
        if (tid < st) {
            red0[tid] += red0[tid + st];
            red1[tid] += red1[tid + st];
            red2[tid] += red2[tid + st];
        }
        __syncthreads();
    }
    const float inv_d = 1.f / (float)CD;
    const float mur = red0[0] * inv_d;
    const float mui = red1[0] * inv_d;
    const float var = red2[0] * inv_d - (mur * mur + mui * mui);
    const float rstd = rsqrtf(var + LN_EPS);

    for (int d = tid; d < CD; d += 256) {
        float zr = (g_dn_re[base + d] - mur) * rstd;
        float zi = (g_dn_im[base + d] - mui) * rstd;
        float g_r = p_ok ? gr[d] : 1.f;
        float g_i = p_ok ? gi[d] : 0.f;
        float b_r = p_ok ? br[d] : 0.f;
        float b_i = p_ok ? bi[d] : 0.f;
        float xre = x_ok ? xr[gbase + d] : 0.f;
        float xim = x_ok ? xi[gbase + d] : 0.f;
        float o_r = g_r * zr - g_i * zi + b_r + xre;
        float o_i = g_r * zi + g_i * zr + b_i + xim;
        if (OUT_MODE == 0) {
            const size_t fo = gbase + d;
            if (fo < out_cap) out[fo] = o_r;
        } else {
            const size_t fo = 2 * (gbase + d);
            if (fo + 1 < out_cap) { out[fo] = o_r; out[fo + 1] = o_i; }
        }
    }
}

// ---------------- host-side binding ----------------
static bool match_sig(const int* s, const long long* want, long long scale) {
    for (int i = 0; i < 13; i++)
        if ((long long)s[i] != want[i] * scale) return false;
    return true;
}

extern "C" void kernel_launch(void* const* d_in, const int* in_sizes, int n_in,
                              void* d_out, int out_size) {
    if (n_in < 13) return;
    for (int i = 0; i < 13; i++) if (d_in[i] == nullptr) return;

    static const long long SIG_DICT[13] =
        {16777216,16777216,16777216,16777216,8192,8192,8192,
         16777216,16777216,2048,2048,2048,2048};
    static const long long SIG_ALPHA[13] =
        {16777216,16777216,16777216,16777216,8192,8192,
         2048,2048,2048,2048,8192,16777216,16777216};

    int order = 0;
    long long unit = 1;
    if (match_sig(in_sizes, SIG_DICT, 1))       { order = 0; unit = 1; }
    else if (match_sig(in_sizes, SIG_ALPHA, 1)) { order = 1; unit = 1; }
    else if (match_sig(in_sizes, SIG_DICT, 4))  { order = 0; unit = 4; }
    else if (match_sig(in_sizes, SIG_ALPHA, 4)) { order = 1; unit = 4; }

    const float *x_re, *x_im, *Wup_re, *Wup_im, *bias_re, *bias_im, *mrb;
    const float *Wd_re, *Wd_im, *g_re, *g_im, *be_re, *be_im;
    size_t sz[13];
    for (int i = 0; i < 13; i++) sz[i] = (size_t)((long long)in_sizes[i] / unit);
    size_t x_lim, wup_lim, wd_lim, bias_lim, ln_lim;

    if (order == 0) {
        x_re   = (const float*)d_in[0];  x_im   = (const float*)d_in[1];
        Wup_re = (const float*)d_in[2];  Wup_im = (const float*)d_in[3];
        bias_re = (const float*)d_in[4]; bias_im = (const float*)d_in[5];
        mrb    = (const float*)d_in[6];
        Wd_re  = (const float*)d_in[7];  Wd_im  = (const float*)d_in[8];
        g_re   = (const float*)d_in[9];  g_im   = (const float*)d_in[10];
        be_re  = (const float*)d_in[11]; be_im  = (const float*)d_in[12];
        x_lim = sz[0] < sz[1] ? sz[0] : sz[1];
        wup_lim = sz[2] < sz[3] ? sz[2] : sz[3];
        bias_lim = sz[4] < sz[5] ? sz[4] : sz[5];
        if (sz[6] < bias_lim) bias_lim = sz[6];
        wd_lim = sz[7] < sz[8] ? sz[7] : sz[8];
        ln_lim = sz[9];
        for (int i = 10; i <= 12; i++) if (sz[i] < ln_lim) ln_lim = sz[i];
    } else {
        Wd_im  = (const float*)d_in[0];  Wd_re  = (const float*)d_in[1];
        Wup_im = (const float*)d_in[2];  Wup_re = (const float*)d_in[3];
        bias_im = (const float*)d_in[4]; bias_re = (const float*)d_in[5];
        be_im  = (const float*)d_in[6];  be_re  = (const float*)d_in[7];
        g_im   = (const float*)d_in[8];  g_re   = (const float*)d_in[9];
        mrb    = (const float*)d_in[10];
        x_im   = (const float*)d_in[11]; x_re   = (const float*)d_in[12];
        wd_lim = sz[0] < sz[1] ? sz[0] : sz[1];
        wup_lim = sz[2] < sz[3] ? sz[2] : sz[3];
        bias_lim = sz[4] < sz[5] ? sz[4] : sz[5];
        if (sz[10] < bias_lim) bias_lim = sz[10];
        ln_lim = sz[6];
        for (int i = 7; i <= 9; i++) if (sz[i] < ln_lim) ln_lim = sz[i];
        x_lim = sz[11] < sz[12] ? sz[11] : sz[12];
    }

    const bool real_only = ((long long)out_size == 16777216LL);
    const size_t out_cap = (size_t)(long long)out_size;

    static bool attr_done = false;
    if (!attr_done) {
        cudaFuncSetAttribute(cgemm_nt<0>, cudaFuncAttributeMaxDynamicSharedMemorySize, SMEM_BYTES);
        cudaFuncSetAttribute(cgemm_nt<1>, cudaFuncAttributeMaxDynamicSharedMemorySize, SMEM_BYTES);
        attr_done = true;
    }

    // ---- pre-convert x, Wup, Wdown to packed bf16 hi/lo planes ----
    uint32_t *cx0, *cx1, *cx2, *cx3, *cu0, *cu1, *cu2, *cu3, *cd0, *cd1, *cd2, *cd3;
    cudaGetSymbolAddress((void**)&cx0, g_cX_hr);  cudaGetSymbolAddress((void**)&cx1, g_cX_lr);
    cudaGetSymbolAddress((void**)&cx2, g_cX_hi);  cudaGetSymbolAddress((void**)&cx3, g_cX_li);
    cudaGetSymbolAddress((void**)&cu0, g_cWu_hr); cudaGetSymbolAddress((void**)&cu1, g_cWu_lr);
    cudaGetSymbolAddress((void**)&cu2, g_cWu_hi); cudaGetSymbolAddress((void**)&cu3, g_cWu_li);
    cudaGetSymbolAddress((void**)&cd0, g_cWd_hr); cudaGetSymbolAddress((void**)&cd1, g_cWd_lr);
    cudaGetSymbolAddress((void**)&cd2, g_cWd_hi); cudaGetSymbolAddress((void**)&cd3, g_cWd_li);

    {
        int gx = (int)((XW + 255) / 256);
        conv_kernel<<<gx, 256>>>(x_re, x_im, cx0, cx1, cx2, cx3, XW, x_lim);
        int gw = (int)((WW + 255) / 256);
        conv_kernel<<<gw, 256>>>(Wup_re, Wup_im, cu0, cu1, cu2, cu3, WW, wup_lim);
        conv_kernel<<<gw, 256>>>(Wd_re, Wd_im, cd0, cd1, cd2, cd3, WW, wd_lim);
    }

    for (int c = 0; c < NCHUNKS; c++) {
        const int mb = c * MCHUNK;
        dim3 g1(CF / BN, MCHUNK / BM);
        cgemm_nt<0><<<g1, THREADS, SMEM_BYTES>>>(bias_re, bias_im, mrb,
                                                 mb, CF, CD, bias_lim);
        dim3 g2(CD / BN, MCHUNK / BM);
        cgemm_nt<1><<<g2, THREADS, SMEM_BYTES>>>(nullptr, nullptr, nullptr,
                                                 mb, CD, CF, 0);
        if (real_only) {
            ln_res_kernel<0><<<MCHUNK, 256>>>(x_re, x_im, g_re, g_im,
                                              be_re, be_im, (float*)d_out, mb,
                                              x_lim, ln_lim, out_cap);
        } else {
            ln_res_kernel<1><<<MCHUNK, 256>>>(x_re, x_im, g_re, g_im,
                                              be_re, be_im, (float*)d_out, mb,
                                              x_lim, ln_lim, out_cap);
        }
    }
}

// round 10
// speedup vs baseline: 3.3692x; 1.1309x over previous
#include <cuda_runtime.h>
#include <cuda_bf16.h>
#include <math.h>
#include <stdint.h>

#define LN_EPS 1e-5f

// Problem constants
constexpr int CB = 4, CS = 2048, CD = 2048, CF = 8192;
constexpr int CM = CB * CS;
constexpr int MCHUNK = 2048;
constexpr int NCHUNKS = CM / MCHUNK;

// GEMM tiling
constexpr int BM = 128, BN = 64, BK = 32;
constexpr int THREADS = 256;     // 8 warps: 4 (M) x 2 (N)
constexpr int RW = 16;           // smem row pitch in words (no padding; swizzled)

// Smem layout (words): per stage, 4 A planes then 4 B planes.
constexpr int A_PL = BM * RW;                // 2048 words per A plane
constexpr int B_PL = BN * RW;                // 1024 words per B plane
constexpr int B_OFF = 4 * A_PL;              // 8192
constexpr int STAGE_W = 4 * A_PL + 4 * B_PL; // 12288 words
constexpr int SMEM_BYTES = 2 * STAGE_W * 4;  // 98304 B -> 2 CTAs/SM

// ---- device-global scratch: packed bf16x2 hi/lo planes (word = k,k+1) ----
constexpr size_t XW = (size_t)CM * CD / 2;
constexpr size_t WW = (size_t)CF * CD / 2;
constexpr size_t UW = (size_t)MCHUNK * CF / 2;
__device__ __align__(16) uint32_t g_cX_hr[XW], g_cX_lr[XW], g_cX_hi[XW], g_cX_li[XW];
__device__ __align__(16) uint32_t g_cWu_hr[WW], g_cWu_lr[WW], g_cWu_hi[WW], g_cWu_li[WW];
__device__ __align__(16) uint32_t g_cWd_hr[WW], g_cWd_lr[WW], g_cWd_hi[WW], g_cWd_li[WW];
__device__ __align__(16) uint32_t g_cUp_hr[UW], g_cUp_lr[UW], g_cUp_hi[UW], g_cUp_li[UW];
__device__ __align__(16) float g_dn_re[(size_t)MCHUNK * CD];
__device__ __align__(16) float g_dn_im[(size_t)MCHUNK * CD];

// Split two fp32 into packed bf16 hi / lo words
__device__ __forceinline__ void split2(float x, float y, uint32_t& hi, uint32_t& lo) {
    __nv_bfloat16 xh = __float2bfloat16_rn(x);
    __nv_bfloat16 yh = __float2bfloat16_rn(y);
    float xr = x - __bfloat162float(xh);
    float yr = y - __bfloat162float(yh);
    __nv_bfloat16 xl = __float2bfloat16_rn(xr);
    __nv_bfloat16 yl = __float2bfloat16_rn(yr);
    hi = (uint32_t)__bfloat16_as_ushort(xh) | ((uint32_t)__bfloat16_as_ushort(yh) << 16);
    lo = (uint32_t)__bfloat16_as_ushort(xl) | ((uint32_t)__bfloat16_as_ushort(yl) << 16);
}

__device__ __forceinline__ void mma16816(float* c, const uint32_t* a, const uint32_t* b) {
    asm volatile(
        "mma.sync.aligned.m16n8k16.row.col.f32.bf16.bf16.f32 "
        "{%0,%1,%2,%3}, {%4,%5,%6,%7}, {%8,%9}, {%0,%1,%2,%3};\n"
        : "+f"(c[0]), "+f"(c[1]), "+f"(c[2]), "+f"(c[3])
        : "r"(a[0]), "r"(a[1]), "r"(a[2]), "r"(a[3]), "r"(b[0]), "r"(b[1]));
}

__device__ __forceinline__ void cpasync16(uint32_t smem_bytes_addr, const void* g) {
    asm volatile("cp.async.cg.shared.global [%0], [%1], 16;\n"
                 :: "r"(smem_bytes_addr), "l"(g));
}
#define CP_COMMIT() asm volatile("cp.async.commit_group;\n")
template <int N>
__device__ __forceinline__ void cp_wait() {
    asm volatile("cp.async.wait_group %0;\n" :: "n"(N));
}

// Swizzled word index within a plane: row pitch 16 words, 16B-chunk XOR.
__device__ __forceinline__ int swz(int row, int kb) {
    return row * RW + ((((kb >> 2) ^ ((row >> 1) & 3)) << 2) | (kb & 3));
}

// Pre-conversion: fp32 planar -> packed bf16x2 hi/lo planes.
__global__ void __launch_bounds__(256)
conv_kernel(const float* __restrict__ re, const float* __restrict__ im,
            uint32_t* __restrict__ hr, uint32_t* __restrict__ lr,
            uint32_t* __restrict__ hi_, uint32_t* __restrict__ li,
            size_t nwords, size_t lim) {
    size_t i = (size_t)blockIdx.x * 256 + threadIdx.x;
    if (i >= nwords) return;
    size_t e = 2 * i;
    float r0 = 0.f, r1 = 0.f, q0 = 0.f, q1 = 0.f;
    if (e + 2 <= lim) {
        float2 v = *reinterpret_cast<const float2*>(re + e);
        float2 w = *reinterpret_cast<const float2*>(im + e);
        r0 = v.x; r1 = v.y; q0 = w.x; q1 = w.y;
    }
    split2(r0, r1, hr[i], lr[i]);
    split2(q0, q1, hi_[i], li[i]);
}

// Complex NT GEMM, pre-converted bf16 operands, cp.async double buffering,
// swizzled smem (2 CTAs/SM).
// PHASE 0: A = g_cX (rows m_base+..), B = g_cWu, epi = bias+modrelu -> g_cUp
// PHASE 1: A = g_cUp (chunk-local), B = g_cWd, epi = plain -> g_dn
template <int PHASE>
__global__ void __launch_bounds__(THREADS, 2)
cgemm_nt(const float* __restrict__ bias_re, const float* __restrict__ bias_im,
         const float* __restrict__ mrb,
         int m_base, int N, int K, size_t bias_lim) {
    extern __shared__ uint32_t s[];
    const uint32_t smem_b = (uint32_t)__cvta_generic_to_shared(s);

    const int tid = threadIdx.x;
    const int lane = tid & 31;
    const int warp = tid >> 5;
    const int wm = warp >> 1;
    const int wn = warp & 1;
    const int g  = lane >> 2;
    const int tg = lane & 3;
    const int m0 = blockIdx.y * BM;
    const int n0 = blockIdx.x * BN;

    const uint32_t* Apl[4];
    const uint32_t* Bpl[4];
    int a_row0;
    if (PHASE == 0) {
        Apl[0] = g_cX_hr; Apl[1] = g_cX_lr; Apl[2] = g_cX_hi; Apl[3] = g_cX_li;
        Bpl[0] = g_cWu_hr; Bpl[1] = g_cWu_lr; Bpl[2] = g_cWu_hi; Bpl[3] = g_cWu_li;
        a_row0 = m_base;
    } else {
        Apl[0] = g_cUp_hr; Apl[1] = g_cUp_lr; Apl[2] = g_cUp_hi; Apl[3] = g_cUp_li;
        Bpl[0] = g_cWd_hr; Bpl[1] = g_cWd_lr; Bpl[2] = g_cWd_hi; Bpl[3] = g_cWd_li;
        a_row0 = 0;
    }
    const int rw = K / 2;  // global plane row length in words

    float accRe[2][4][4], accIm[2][4][4];
#pragma unroll
    for (int mi = 0; mi < 2; mi++)
#pragma unroll
        for (int ni = 0; ni < 4; ni++)
#pragma unroll
            for (int r = 0; r < 4; r++) { accRe[mi][ni][r] = 0.f; accIm[mi][ni][r] = 0.f; }

    // Stage loader: 3072 16B chunks / 256 threads = 12 each.
    auto load_stage = [&](int buf, int k0) {
        const int kw0 = k0 >> 1;
        const uint32_t sb = smem_b + (uint32_t)buf * STAGE_W * 4;
#pragma unroll
        for (int t = 0; t < 8; t++) {
            int c = tid + t * THREADS;       // A: 0..2047
            int p = c >> 9;
            int r = (c >> 2) & 127;
            int kc = c & 3;
            const uint32_t* src = Apl[p] + (size_t)(a_row0 + m0 + r) * rw + kw0 + kc * 4;
            int w = r * RW + ((kc ^ ((r >> 1) & 3)) << 2);
            cpasync16(sb + (uint32_t)(p * A_PL + w) * 4, src);
        }
#pragma unroll
        for (int t = 0; t < 4; t++) {
            int c = tid + t * THREADS;       // B: 0..1023
            int p = c >> 8;
            int r = (c >> 2) & 63;
            int kc = c & 3;
            const uint32_t* src = Bpl[p] + (size_t)(n0 + r) * rw + kw0 + kc * 4;
            int w = r * RW + ((kc ^ ((r >> 1) & 3)) << 2);
            cpasync16(sb + (uint32_t)(B_OFF + p * B_PL + w) * 4, src);
        }
        CP_COMMIT();
    };

    const int NK = K / BK;
    load_stage(0, 0);

    for (int it = 0; it < NK; it++) {
        if (it + 1 < NK) {
            load_stage((it + 1) & 1, (it + 1) * BK);
            cp_wait<1>();
        } else {
            cp_wait<0>();
        }
        __syncthreads();

        const int st = (it & 1) * STAGE_W;
        const int AHR = st, ALR = st + A_PL, AHI = st + 2 * A_PL, ALI = st + 3 * A_PL;
        const int BHR = st + B_OFF, BLR = BHR + B_PL, BHI = BHR + 2 * B_PL, BLI = BHR + 3 * B_PL;

#pragma unroll
        for (int ks = 0; ks < 2; ks++) {
            uint32_t Brh[4][2], Brl[4][2], Bih[4][2], Bil[4][2];
#pragma unroll
            for (int ni = 0; ni < 4; ni++) {
                const int rb = wn * 32 + ni * 8 + g;
                const int w0 = swz(rb, ks * 8 + tg);
                const int w1 = swz(rb, ks * 8 + tg + 4);
                Brh[ni][0] = s[BHR + w0]; Brh[ni][1] = s[BHR + w1];
                Brl[ni][0] = s[BLR + w0]; Brl[ni][1] = s[BLR + w1];
                Bih[ni][0] = s[BHI + w0]; Bih[ni][1] = s[BHI + w1];
                Bil[ni][0] = s[BLI + w0]; Bil[ni][1] = s[BLI + w1];
            }
            uint32_t Arh[2][4], Arl[2][4], Aih[2][4], Ail[2][4], nAih[2][4], nAil[2][4];
#pragma unroll
            for (int mi = 0; mi < 2; mi++) {
                const int r0 = wm * 32 + mi * 16 + g;
                const int r1 = r0 + 8;
                const int u0 = swz(r0, ks * 8 + tg);
                const int u1 = swz(r1, ks * 8 + tg);
                const int u2 = swz(r0, ks * 8 + tg + 4);
                const int u3 = swz(r1, ks * 8 + tg + 4);
                Arh[mi][0] = s[AHR + u0]; Arh[mi][1] = s[AHR + u1];
                Arh[mi][2] = s[AHR + u2]; Arh[mi][3] = s[AHR + u3];
                Arl[mi][0] = s[ALR + u0]; Arl[mi][1] = s[ALR + u1];
                Arl[mi][2] = s[ALR + u2]; Arl[mi][3] = s[ALR + u3];
                Aih[mi][0] = s[AHI + u0]; Aih[mi][1] = s[AHI + u1];
                Aih[mi][2] = s[AHI + u2]; Aih[mi][3] = s[AHI + u3];
                Ail[mi][0] = s[ALI + u0]; Ail[mi][1] = s[ALI + u1];
                Ail[mi][2] = s[ALI + u2]; Ail[mi][3] = s[ALI + u3];
#pragma unroll
                for (int r = 0; r < 4; r++) {
                    nAih[mi][r] = Aih[mi][r] ^ 0x80008000u;
                    nAil[mi][r] = Ail[mi][r] ^ 0x80008000u;
                }
            }
#pragma unroll
            for (int mi = 0; mi < 2; mi++) {
#pragma unroll
                for (int ni = 0; ni < 4; ni++) {
                    mma16816(accRe[mi][ni], Arh[mi],  Brh[ni]);
                    mma16816(accRe[mi][ni], Arh[mi],  Brl[ni]);
                    mma16816(accRe[mi][ni], Arl[mi],  Brh[ni]);
                    mma16816(accRe[mi][ni], nAih[mi], Bih[ni]);
                    mma16816(accRe[mi][ni], nAih[mi], Bil[ni]);
                    mma16816(accRe[mi][ni], nAil[mi], Bih[ni]);
                    mma16816(accIm[mi][ni], Arh[mi],  Bih[ni]);
                    mma16816(accIm[mi][ni], Arh[mi],  Bil[ni]);
                    mma16816(accIm[mi][ni], Arl[mi],  Bih[ni]);
                    mma16816(accIm[mi][ni], Aih[mi],  Brh[ni]);
                    mma16816(accIm[mi][ni], Aih[mi],  Brl[ni]);
                    mma16816(accIm[mi][ni], Ail[mi],  Brh[ni]);
                }
            }
        }
        __syncthreads();
    }

    // ---- epilogue ----
    const bool bias_ok = (PHASE != 0) || ((size_t)n0 + BN <= bias_lim);
#pragma unroll
    for (int mi = 0; mi < 2; mi++) {
#pragma unroll
        for (int ni = 0; ni < 4; ni++) {
            const int col = n0 + wn * 32 + ni * 8 + 2 * tg;   // even
#pragma unroll
            for (int h = 0; h < 2; h++) {
                const int row = m0 + wm * 32 + mi * 16 + g + h * 8;
                float re0 = accRe[mi][ni][2 * h], re1 = accRe[mi][ni][2 * h + 1];
                float im0 = accIm[mi][ni][2 * h], im1 = accIm[mi][ni][2 * h + 1];
                if (PHASE == 0) {
                    float br0 = 0.f, br1 = 0.f, bi0 = 0.f, bi1 = 0.f, mb0 = 0.f, mb1 = 0.f;
                    if (bias_ok) {
                        br0 = bias_re[col]; br1 = bias_re[col + 1];
                        bi0 = bias_im[col]; bi1 = bias_im[col + 1];
                        mb0 = mrb[col];     mb1 = mrb[col + 1];
                    }
                    re0 += br0; im0 += bi0; re1 += br1; im1 += bi1;
                    float mag0 = sqrtf(re0 * re0 + im0 * im0);
                    float mag1 = sqrtf(re1 * re1 + im1 * im1);
                    float s0 = fmaxf(mag0 + mb0, 0.f) / (mag0 + LN_EPS);
                    float s1 = fmaxf(mag1 + mb1, 0.f) / (mag1 + LN_EPS);
                    re0 *= s0; im0 *= s0; re1 *= s1; im1 *= s1;
                    const size_t wo = (size_t)row * (N / 2) + (col >> 1);
                    split2(re0, re1, g_cUp_hr[wo], g_cUp_lr[wo]);
                    split2(im0, im1, g_cUp_hi[wo], g_cUp_li[wo]);
                } else {
                    const size_t off = (size_t)row * N + col;
                    *reinterpret_cast<float2*>(g_dn_re + off) = make_float2(re0, re1);
                    *reinterpret_cast<float2*>(g_dn_im + off) = make_float2(im0, im1);
                }
            }
        }
    }
}

// Complex LayerNorm over D + residual, one block per (chunk-local) token row.
template <int OUT_MODE>
__global__ void __launch_bounds__(256)
ln_res_kernel(const float* __restrict__ xr, const float* __restrict__ xi,
              const float* __restrict__ gr, const float* __restrict__ gi,
              const float* __restrict__ br, const float* __restrict__ bi,
              float* __restrict__ out, int m_base,
              size_t x_lim, size_t p_lim, size_t out_cap) {
    const int m = blockIdx.x;
    const size_t base = (size_t)m * CD;
    const size_t gbase = (size_t)(m_base + m) * CD;
    const int tid = threadIdx.x;
    const bool x_ok = (gbase + CD) <= x_lim;
    const bool p_ok = (size_t)CD <= p_lim;

    float sr = 0.f, si = 0.f, sq = 0.f;
    for (int d = tid; d < CD; d += 256) {
        float r = g_dn_re[base + d];
        float q = g_dn_im[base + d];
        sr += r; si += q; sq += r * r + q * q;
    }
    __shared__ float red0[256], red1[256], red2[256];
    red0[tid] = sr; red1[tid] = si; red2[tid] = sq;
    __syncthreads();
    for (int st = 128; st > 0; st >>= 1) {
        if (tid < st) {
            red0[tid] += red0[tid + st];
            red1[tid] += red1[tid + st];
            red2[tid] += red2[tid + st];
        }
        __syncthreads();
    }
    const float inv_d = 1.f / (float)CD;
    const float mur = red0[0] * inv_d;
    const float mui = red1[0] * inv_d;
    const float var = red2[0] * inv_d - (mur * mur + mui * mui);
    const float rstd = rsqrtf(var + LN_EPS);

    for (int d = tid; d < CD; d += 256) {
        float zr = (g_dn_re[base + d] - mur) * rstd;
        float zi = (g_dn_im[base + d] - mui) * rstd;
        float g_r = p_ok ? gr[d] : 1.f;
        float g_i = p_ok ? gi[d] : 0.f;
        float b_r = p_ok ? br[d] : 0.f;
        float b_i = p_ok ? bi[d] : 0.f;
        float xre = x_ok ? xr[gbase + d] : 0.f;
        float xim = x_ok ? xi[gbase + d] : 0.f;
        float o_r = g_r * zr - g_i * zi + b_r + xre;
        float o_i = g_r * zi + g_i * zr + b_i + xim;
        if (OUT_MODE == 0) {
            const size_t fo = gbase + d;
            if (fo < out_cap) out[fo] = o_r;
        } else {
            const size_t fo = 2 * (gbase + d);
            if (fo + 1 < out_cap) { out[fo] = o_r; out[fo + 1] = o_i; }
        }
    }
}

// ---------------- host-side binding ----------------
static bool match_sig(const int* s, const long long* want, long long scale) {
    for (int i = 0; i < 13; i++)
        if ((long long)s[i] != want[i] * scale) return false;
    return true;
}

extern "C" void kernel_launch(void* const* d_in, const int* in_sizes, int n_in,
                              void* d_out, int out_size) {
    if (n_in < 13) return;
    for (int i = 0; i < 13; i++) if (d_in[i] == nullptr) return;

    static const long long SIG_DICT[13] =
        {16777216,16777216,16777216,16777216,8192,8192,8192,
         16777216,16777216,2048,2048,2048,2048};
    static const long long SIG_ALPHA[13] =
        {16777216,16777216,16777216,16777216,8192,8192,
         2048,2048,2048,2048,8192,16777216,16777216};

    int order = 0;
    long long unit = 1;
    if (match_sig(in_sizes, SIG_DICT, 1))       { order = 0; unit = 1; }
    else if (match_sig(in_sizes, SIG_ALPHA, 1)) { order = 1; unit = 1; }
    else if (match_sig(in_sizes, SIG_DICT, 4))  { order = 0; unit = 4; }
    else if (match_sig(in_sizes, SIG_ALPHA, 4)) { order = 1; unit = 4; }

    const float *x_re, *x_im, *Wup_re, *Wup_im, *bias_re, *bias_im, *mrb;
    const float *Wd_re, *Wd_im, *g_re, *g_im, *be_re, *be_im;
    size_t sz[13];
    for (int i = 0; i < 13; i++) sz[i] = (size_t)((long long)in_sizes[i] / unit);
    size_t x_lim, wup_lim, wd_lim, bias_lim, ln_lim;

    if (order == 0) {
        x_re   = (const float*)d_in[0];  x_im   = (const float*)d_in[1];
        Wup_re = (const float*)d_in[2];  Wup_im = (const float*)d_in[3];
        bias_re = (const float*)d_in[4]; bias_im = (const float*)d_in[5];
        mrb    = (const float*)d_in[6];
        Wd_re  = (const float*)d_in[7];  Wd_im  = (const float*)d_in[8];
        g_re   = (const float*)d_in[9];  g_im   = (const float*)d_in[10];
        be_re  = (const float*)d_in[11]; be_im  = (const float*)d_in[12];
        x_lim = sz[0] < sz[1] ? sz[0] : sz[1];
        wup_lim = sz[2] < sz[3] ? sz[2] : sz[3];
        bias_lim = sz[4] < sz[5] ? sz[4] : sz[5];
        if (sz[6] < bias_lim) bias_lim = sz[6];
        wd_lim = sz[7] < sz[8] ? sz[7] : sz[8];
        ln_lim = sz[9];
        for (int i = 10; i <= 12; i++) if (sz[i] < ln_lim) ln_lim = sz[i];
    } else {
        Wd_im  = (const float*)d_in[0];  Wd_re  = (const float*)d_in[1];
        Wup_im = (const float*)d_in[2];  Wup_re = (const float*)d_in[3];
        bias_im = (const float*)d_in[4]; bias_re = (const float*)d_in[5];
        be_im  = (const float*)d_in[6];  be_re  = (const float*)d_in[7];
        g_im   = (const float*)d_in[8];  g_re   = (const float*)d_in[9];
        mrb    = (const float*)d_in[10];
        x_im   = (const float*)d_in[11]; x_re   = (const float*)d_in[12];
        wd_lim = sz[0] < sz[1] ? sz[0] : sz[1];
        wup_lim = sz[2] < sz[3] ? sz[2] : sz[3];
        bias_lim = sz[4] < sz[5] ? sz[4] : sz[5];
        if (sz[10] < bias_lim) bias_lim = sz[10];
        ln_lim = sz[6];
        for (int i = 7; i <= 9; i++) if (sz[i] < ln_lim) ln_lim = sz[i];
        x_lim = sz[11] < sz[12] ? sz[11] : sz[12];
    }

    const bool real_only = ((long long)out_size == 16777216LL);
    const size_t out_cap = (size_t)(long long)out_size;

    static bool attr_done = false;
    if (!attr_done) {
        cudaFuncSetAttribute(cgemm_nt<0>, cudaFuncAttributeMaxDynamicSharedMemorySize, SMEM_BYTES);
        cudaFuncSetAttribute(cgemm_nt<1>, cudaFuncAttributeMaxDynamicSharedMemorySize, SMEM_BYTES);
        attr_done = true;
    }

    // ---- pre-convert x, Wup, Wdown to packed bf16 hi/lo planes ----
    uint32_t *cx0, *cx1, *cx2, *cx3, *cu0, *cu1, *cu2, *cu3, *cd0, *cd1, *cd2, *cd3;
    cudaGetSymbolAddress((void**)&cx0, g_cX_hr);  cudaGetSymbolAddress((void**)&cx1, g_cX_lr);
    cudaGetSymbolAddress((void**)&cx2, g_cX_hi);  cudaGetSymbolAddress((void**)&cx3, g_cX_li);
    cudaGetSymbolAddress((void**)&cu0, g_cWu_hr); cudaGetSymbolAddress((void**)&cu1, g_cWu_lr);
    cudaGetSymbolAddress((void**)&cu2, g_cWu_hi); cudaGetSymbolAddress((void**)&cu3, g_cWu_li);
    cudaGetSymbolAddress((void**)&cd0, g_cWd_hr); cudaGetSymbolAddress((void**)&cd1, g_cWd_lr);
    cudaGetSymbolAddress((void**)&cd2, g_cWd_hi); cudaGetSymbolAddress((void**)&cd3, g_cWd_li);

    {
        int gx = (int)((XW + 255) / 256);
        conv_kernel<<<gx, 256>>>(x_re, x_im, cx0, cx1, cx2, cx3, XW, x_lim);
        int gw = (int)((WW + 255) / 256);
        conv_kernel<<<gw, 256>>>(Wup_re, Wup_im, cu0, cu1, cu2, cu3, WW, wup_lim);
        conv_kernel<<<gw, 256>>>(Wd_re, Wd_im, cd0, cd1, cd2, cd3, WW, wd_lim);
    }

    for (int c = 0; c < NCHUNKS; c++) {
        const int mb = c * MCHUNK;
        dim3 g1(CF / BN, MCHUNK / BM);
        cgemm_nt<0><<<g1, THREADS, SMEM_BYTES>>>(bias_re, bias_im, mrb,
                                                 mb, CF, CD, bias_lim);
        dim3 g2(CD / BN, MCHUNK / BM);
        cgemm_nt<1><<<g2, THREADS, SMEM_BYTES>>>(nullptr, nullptr, nullptr,
                                                 mb, CD, CF, 0);
        if (real_only) {
            ln_res_kernel<0><<<MCHUNK, 256>>>(x_re, x_im, g_re, g_im,
                                              be_re, be_im, (float*)d_out, mb,
                                              x_lim, ln_lim, out_cap);
        } else {
            ln_res_kernel<1><<<MCHUNK, 256>>>(x_re, x_im, g_re, g_im,
                                              be_re, be_im, (float*)d_out, mb,
                                              x_lim, ln_lim, out_cap);
        }
    }
}